// round 8
// baseline (speedup 1.0000x reference)
#include <cuda_runtime.h>
#include <cuda_bf16.h>

#define IMG_H 384
#define IMG_W 640
#define N_PLANES 96            // 32 * 3
#define WIN 11
#define HALO 5
#define OUT_W_TILE 246
#define NX 3                   // 246 + 246 + 148 = 640
#define NY 3
#define ROWS_PER_BLK (IMG_H / NY)       // 128
#define CHUNK 16
#define NCHUNKS (ROWS_PER_BLK / CHUNK)  // 8
#define NTHREADS 256

// SMEM: two packed-ull arrays, CHUNK rows x VS2 ull each.
//   A01 : (Sum p, Sum t)           packed f32x2
//   A234: (Sum p^2+t^2, Sum p*t)   packed f32x2
// VS2=258 even -> hbase even -> 16B-aligned paired loads; f4 index mod 8 =
// (hrow + i) mod 8 -> 8-lane phases hit distinct 16B granules: conflict-free.
#define VS2 258
#define A234_U (CHUNK * VS2)                 // 4128 ull
#define SMEM_BYTES (2 * CHUNK * VS2 * 8 + 256)   // 66,304 B (incl. overread pad)

#define C1F 1e-4f
#define C2F 9e-4f
#define N_BLOCKS (NX * NY * N_PLANES)  // 864

__device__ float g_partials[N_BLOCKS];
__device__ unsigned int g_count = 0;

// ---- packed f32x2 helpers (Blackwell FFMA2 path) ----
__device__ __forceinline__ unsigned long long pk2(float lo, float hi) {
    unsigned long long r;
    asm("mov.b64 %0, {%1, %2};" : "=l"(r) : "f"(lo), "f"(hi));
    return r;
}
__device__ __forceinline__ void upk2(unsigned long long v, float& lo, float& hi) {
    asm("mov.b64 {%0, %1}, %2;" : "=f"(lo), "=f"(hi) : "l"(v));
}
__device__ __forceinline__ unsigned long long add2(unsigned long long a, unsigned long long b) {
    unsigned long long r;
    asm("add.rn.f32x2 %0, %1, %2;" : "=l"(r) : "l"(a), "l"(b));
    return r;
}
__device__ __forceinline__ unsigned long long fma2(unsigned long long a, unsigned long long b,
                                                   unsigned long long c) {
    unsigned long long r;
    asm("fma.rn.f32x2 %0, %1, %2, %3;" : "=l"(r) : "l"(a), "l"(b), "l"(c));
    return r;
}
#define NEG1_X2 0xBF800000BF800000ULL   // packed (-1.0f, -1.0f)

__global__ __launch_bounds__(NTHREADS, 3)
void ssim_main(const float* __restrict__ pred, const float* __restrict__ targ,
               float* __restrict__ out) {
    extern __shared__ float smem[];
    unsigned long long* __restrict__ sm64 =
        reinterpret_cast<unsigned long long*>(smem);

    const int b = blockIdx.x;
    const int xt = b % NX;
    const int yt = (b / NX) % NY;
    const int plane = b / (NX * NY);

    const int x0 = xt * OUT_W_TILE;
    const int outw = min(OUT_W_TILE, IMG_W - x0);   // 246 or 148
    const int inw = outw + 2 * HALO;                // 256 or 158
    const int r0 = yt * ROWS_PER_BLK;

    const size_t poff = (size_t)plane * (IMG_H * IMG_W);
    const float* __restrict__ P = pred + poff;
    const float* __restrict__ T = targ + poff;

    // ---------- vertical-pass identity ----------
    const int c = threadIdx.x;               // buffer column
    const int gx = x0 - HALO + c;            // global column
    const bool cvalid = (c < inw);
    const bool colin = cvalid && (gx >= 0) && (gx < IMG_W);

    unsigned long long vs01 = 0ULL;          // packed (sum p, sum t)
    float vs23 = 0.f;                        // sum (p*p + t*t)
    float vs4 = 0.f;                         // sum (p*t)

    #pragma unroll
    for (int k = -HALO; k < HALO; ++k) {
        const int rr = r0 + k;
        float p = 0.f, t = 0.f;
        if (colin && rr >= 0 && rr < IMG_H) {
            p = P[rr * IMG_W + gx];
            t = T[rr * IMG_W + gx];
        }
        vs01 = add2(vs01, pk2(p, t));
        vs23 = fmaf(p, p, fmaf(t, t, vs23));
        vs4  = fmaf(p, t, vs4);
    }

    // ---------- horizontal-pass identity: 16 rows x 16 segments of 16 ----------
    const int hrow = threadIdx.x & (CHUNK - 1);   // 0..15
    const int hseg = threadIdx.x >> 4;            // 0..15
    const int xs = hseg * 16;
    const bool segvalid = (xs < outw);
    const int nvalid = segvalid ? min(16, outw - xs) : 0;

    float acc = 0.f;
    const float KK   = 1.0f / 121.0f;
    const float TWOK = 2.0f / 121.0f;
    const float K2C  = KK * KK;
    const float TK2  = 2.0f * K2C;
    const float C12  = C1F + C2F;

    const int hbase = hrow * VS2 + xs;            // even

    for (int ch = 0; ch < NCHUNKS; ++ch) {
        const int rbase = r0 + ch * CHUNK;

        // ===== vertical pass: CHUNK rows of packed box-column sums =====
        #pragma unroll
        for (int i = 0; i < CHUNK; ++i) {
            const int r = rbase + i;
            {   // incoming row r+5
                const int rr = r + HALO;
                float p = 0.f, t = 0.f;
                if (colin && rr < IMG_H) {
                    p = P[rr * IMG_W + gx];
                    t = T[rr * IMG_W + gx];
                }
                vs01 = add2(vs01, pk2(p, t));
                vs23 = fmaf(p, p, fmaf(t, t, vs23));
                vs4  = fmaf(p, t, vs4);
            }
            if (cvalid) {
                sm64[i * VS2 + c]          = vs01;             // STS.64
                sm64[A234_U + i * VS2 + c] = pk2(vs23, vs4);   // STS.64
            }
            {   // outgoing row r-5 (L1/L2 reload)
                const int ro = r - HALO;
                float p = 0.f, t = 0.f;
                if (colin && ro >= 0) {
                    p = P[ro * IMG_W + gx];
                    t = T[ro * IMG_W + gx];
                }
                vs01 = fma2(pk2(p, t), NEG1_X2, vs01);
                vs23 = fmaf(-p, p, fmaf(-t, t, vs23));
                vs4  = fmaf(-p, t, vs4);
            }
        }
        __syncthreads();

        // ===== horizontal pass: interleaved rolling windows, JIT paired loads =====
        if (segvalid) {
            const ulonglong2* __restrict__ pa =
                reinterpret_cast<const ulonglong2*>(sm64 + hbase);
            const ulonglong2* __restrict__ pb =
                reinterpret_cast<const ulonglong2*>(sm64 + A234_U + hbase);

            unsigned long long a[26], bw[26];

            // warmup: entries 0..11 for both windows (6 LDS.128 each)
            #pragma unroll
            for (int k = 0; k < 6; ++k) {
                ulonglong2 u = pa[k]; a[2 * k] = u.x;  a[2 * k + 1] = u.y;
                ulonglong2 v = pb[k]; bw[2 * k] = v.x; bw[2 * k + 1] = v.y;
            }
            unsigned long long SA = a[0], SB = bw[0];
            #pragma unroll
            for (int k = 1; k < WIN; ++k) { SA = add2(SA, a[k]); SB = add2(SB, bw[k]); }

            #pragma unroll
            for (int j = 0; j < 16; ++j) {
                float sp, st;   upk2(SA, sp, st);
                float sqq, spt; upk2(SB, sqq, spt);
                float n1 = fmaf(TK2, sp * st, C1F);
                float d1 = fmaf(K2C, fmaf(sp, sp, st * st), C1F);
                float n2 = fmaf(TWOK, spt, C12 - n1);
                float d2 = fmaf(KK, sqq, C12 - d1);
                float r = __fdividef(n1 * n2, d1 * d2);
                if (j < nvalid) acc += r;

                if (j < 15) {
                    if (j & 1) {   // odd step: load next entry pair (j+11, j+12)
                        const int k2 = (j + 11) >> 1;
                        ulonglong2 u = pa[k2];
                        a[j + 11] = u.x;  a[j + 12] = u.y;
                        ulonglong2 v = pb[k2];
                        bw[j + 11] = v.x; bw[j + 12] = v.y;
                    }
                    SA = add2(SA, a[j + WIN]);
                    SA = fma2(a[j], NEG1_X2, SA);
                    SB = add2(SB, bw[j + WIN]);
                    SB = fma2(bw[j], NEG1_X2, SB);
                }
            }
        }
        __syncthreads();
    }

    // ---------- deterministic block reduction ----------
    smem[threadIdx.x] = acc;
    __syncthreads();
    #pragma unroll
    for (int off = NTHREADS / 2; off > 0; off >>= 1) {
        if (threadIdx.x < off) smem[threadIdx.x] += smem[threadIdx.x + off];
        __syncthreads();
    }

    // ---------- fused finalize: last block reduces all partials ----------
    __shared__ bool s_last;
    if (threadIdx.x == 0) {
        g_partials[b] = smem[0];
        __threadfence();
        unsigned int n = atomicAdd(&g_count, 1u);
        s_last = (n == (unsigned int)(N_BLOCKS - 1));
    }
    __syncthreads();
    if (s_last) {
        double* sd = reinterpret_cast<double*>(smem);
        if (threadIdx.x < 128) {
            double s = 0.0;
            if (threadIdx.x < 96) {
                #pragma unroll
                for (int q = 0; q < 9; ++q)      // 96 * 9 = 864, fixed order
                    s += (double)g_partials[threadIdx.x * 9 + q];
            }
            sd[threadIdx.x] = s;
        }
        __syncthreads();
        #pragma unroll
        for (int off = 64; off > 0; off >>= 1) {
            if (threadIdx.x < off) sd[threadIdx.x] += sd[threadIdx.x + off];
            __syncthreads();
        }
        if (threadIdx.x == 0) {
            const double n = (double)N_PLANES * IMG_H * IMG_W;   // 23,592,960
            out[0] = (float)(1.0 - sd[0] / n);
            g_count = 0u;                         // reset for next graph replay
        }
    }
}

extern "C" void kernel_launch(void* const* d_in, const int* in_sizes, int n_in,
                              void* d_out, int out_size) {
    const float* pred = (const float*)d_in[0];
    const float* targ = (const float*)d_in[1];
    float* out = (float*)d_out;

    cudaFuncSetAttribute(ssim_main, cudaFuncAttributeMaxDynamicSharedMemorySize,
                         SMEM_BYTES);
    ssim_main<<<N_BLOCKS, NTHREADS, SMEM_BYTES>>>(pred, targ, out);
}

// round 9
// speedup vs baseline: 1.5623x; 1.5623x over previous
#include <cuda_runtime.h>
#include <cuda_bf16.h>

#define IMG_H 384
#define IMG_W 640
#define N_PLANES 96            // 32 * 3
#define WIN 11
#define HALO 5
#define OUT_W_TILE 246
#define NX 3                   // 246 + 246 + 148 = 640
#define NY 2
#define ROWS_PER_BLK (IMG_H / NY)       // 192
#define CHUNK 16
#define NCHUNKS (ROWS_PER_BLK / CHUNK)  // 12
#define NTHREADS 256

// SMEM layout (float units):
//   A01: CHUNK rows of VS2 float2 pairs (Sp, St)    -- packed
//   A23: CHUNK rows of VS1 floats      (Spp + Stt)
//   A4 : CHUNK rows of VS1 floats      (Spt)
// VS2=258: 2*VS2 = 516 == 4 (mod 32)  -> conflict-free 8-lane LDS.128 phases
// VS1=260: VS1 == 4 (mod 32)          -> conflict-free 8-lane LDS.128 phases
#define VS2 258
#define VS1 260
#define A01_OFF 0
#define A23_OFF (CHUNK * VS2 * 2)            // 8256
#define A4_OFF  (A23_OFF + CHUNK * VS1)      // 12416
#define SMEM_FLOATS (A4_OFF + CHUNK * VS1 + 64)  // 16640 (incl. overread pad)
#define SMEM_BYTES (SMEM_FLOATS * 4)             // 66560 B

#define C1F 1e-4f
#define C2F 9e-4f
#define N_BLOCKS (NX * NY * N_PLANES)  // 576

__device__ float g_partials[N_BLOCKS];
__device__ unsigned int g_count = 0;

// ---- packed f32x2 helpers (Blackwell FFMA2 path) ----
__device__ __forceinline__ unsigned long long pk2(float lo, float hi) {
    unsigned long long r;
    asm("mov.b64 %0, {%1, %2};" : "=l"(r) : "f"(lo), "f"(hi));
    return r;
}
__device__ __forceinline__ void upk2(unsigned long long v, float& lo, float& hi) {
    asm("mov.b64 {%0, %1}, %2;" : "=f"(lo), "=f"(hi) : "l"(v));
}
__device__ __forceinline__ unsigned long long add2(unsigned long long a, unsigned long long b) {
    unsigned long long r;
    asm("add.rn.f32x2 %0, %1, %2;" : "=l"(r) : "l"(a), "l"(b));
    return r;
}
__device__ __forceinline__ unsigned long long fma2(unsigned long long a, unsigned long long b,
                                                   unsigned long long c) {
    unsigned long long r;
    asm("fma.rn.f32x2 %0, %1, %2, %3;" : "=l"(r) : "l"(a), "l"(b), "l"(c));
    return r;
}
#define NEG1_X2 0xBF800000BF800000ULL   // packed (-1.0f, -1.0f)

__global__ __launch_bounds__(NTHREADS, 2)
void ssim_main(const float* __restrict__ pred, const float* __restrict__ targ,
               float* __restrict__ out) {
    extern __shared__ float smem[];

    const int b = blockIdx.x;
    const int xt = b % NX;
    const int yt = (b / NX) % NY;
    const int plane = b / (NX * NY);

    const int x0 = xt * OUT_W_TILE;
    const int outw = min(OUT_W_TILE, IMG_W - x0);   // 246 or 148
    const int inw = outw + 2 * HALO;
    const int r0 = yt * ROWS_PER_BLK;

    const size_t poff = (size_t)plane * (IMG_H * IMG_W);
    const float* __restrict__ P = pred + poff;
    const float* __restrict__ T = targ + poff;

    // ---------- vertical-pass identity ----------
    const int c = threadIdx.x;               // buffer column
    const int gx = x0 - HALO + c;            // global column
    const bool cvalid = (c < inw);
    const bool colin = cvalid && (gx >= 0) && (gx < IMG_W);

    unsigned long long vs01 = 0ULL;          // packed (sum p, sum t)
    float vs23 = 0.f;                        // sum (p*p + t*t)
    float vs4 = 0.f;                         // sum (p*t)

    // 10-deep register shift-register of packed (p,t) input rows.
    // Row loaded at iter r (as r+5) is consumed (subtracted) at iter r+10.
    unsigned long long hist[10];

    // warmup: rows r0-5 .. r0+4
    #pragma unroll
    for (int k = 0; k < 10; ++k) {
        const int rr = r0 - HALO + k;
        float p = 0.f, t = 0.f;
        if (colin && rr >= 0) {              // rr < IMG_H always in warmup
            p = P[rr * IMG_W + gx];
            t = T[rr * IMG_W + gx];
        }
        hist[k] = pk2(p, t);
        vs01 = add2(vs01, pk2(p, t));
        vs23 = fmaf(p, p, fmaf(t, t, vs23));
        vs4  = fmaf(p, t, vs4);
    }

    // ---------- horizontal-pass identity ----------
    const int hrow = threadIdx.x & (CHUNK - 1);   // 0..15
    const int hseg = threadIdx.x >> 4;            // 0..15
    const int xs = hseg * 16;
    const bool segvalid = (xs < outw);
    const int nvalid = segvalid ? min(16, outw - xs) : 0;

    float acc = 0.f;
    const float KK  = 1.0f / 121.0f;
    const float K2C = KK * KK;
    const float TK2 = 2.0f * K2C;
    const float C12 = C1F + C2F;

    for (int ch = 0; ch < NCHUNKS; ++ch) {
        const int rbase = r0 + ch * CHUNK;

        // ===== vertical pass: CHUNK rows, incoming LDG only =====
        #pragma unroll
        for (int i = 0; i < CHUNK; ++i) {
            // incoming row r+5
            const int rr = rbase + i + HALO;
            float p = 0.f, t = 0.f;
            if (colin && rr < IMG_H) {
                p = P[rr * IMG_W + gx];
                t = T[rr * IMG_W + gx];
            }
            const unsigned long long nw = pk2(p, t);
            vs01 = add2(vs01, nw);
            vs23 = fmaf(p, p, fmaf(t, t, vs23));
            vs4  = fmaf(p, t, vs4);

            if (cvalid) {
                *reinterpret_cast<unsigned long long*>(
                    &smem[A01_OFF + (i * VS2 + c) * 2]) = vs01;     // STS.64
                smem[A23_OFF + i * VS1 + c] = vs23;
                smem[A4_OFF  + i * VS1 + c] = vs4;
            }

            // outgoing row r-5 from register history (no reload)
            {
                float po, to; upk2(hist[0], po, to);
                vs01 = fma2(hist[0], NEG1_X2, vs01);
                vs23 = fmaf(-po, po, fmaf(-to, to, vs23));
                vs4  = fmaf(-po, to, vs4);
            }
            #pragma unroll
            for (int k = 0; k < 9; ++k) hist[k] = hist[k + 1];
            hist[9] = nw;
        }
        __syncthreads();

        // ===== horizontal pass: vectorized register-window sliding sums =====
        if (segvalid) {
            float numA[16], denF[16];

            // Pass A: packed (Sp, St) -> numA = 2k^2*ab + C1, denA = k^2*(a^2+b^2) + C1
            {
                const ulonglong2* b01 =
                    reinterpret_cast<const ulonglong2*>(smem) + ((hrow * VS2 + xs) >> 1);
                unsigned long long v[28];
                #pragma unroll
                for (int k = 0; k < 14; ++k) {
                    ulonglong2 u = b01[k];          // LDS.128, conflict-free
                    v[2 * k] = u.x; v[2 * k + 1] = u.y;
                }
                unsigned long long S = v[0];
                #pragma unroll
                for (int k = 1; k < WIN; ++k) S = add2(S, v[k]);
                #pragma unroll
                for (int j = 0; j < 16; ++j) {
                    float a, bb; upk2(S, a, bb);
                    float ab = a * bb;
                    float V  = fmaf(a, a, bb * bb);
                    numA[j] = fmaf(TK2, ab, C1F);
                    denF[j] = fmaf(K2C, V, C1F);    // den1 (for now)
                    if (j < 15) {
                        S = add2(S, v[j + WIN]);
                        S = fma2(v[j], NEG1_X2, S);
                    }
                }
            }
            // Pass B: S = box sum of (pp+tt); den2 = k*S - den1 + (C1+C2); denF = den1*den2
            {
                const float4* b23 =
                    reinterpret_cast<const float4*>(&smem[A23_OFF + hrow * VS1 + xs]);
                float w[28];
                #pragma unroll
                for (int k = 0; k < 7; ++k) {
                    float4 u = b23[k];
                    w[4*k] = u.x; w[4*k+1] = u.y; w[4*k+2] = u.z; w[4*k+3] = u.w;
                }
                float S = w[0];
                #pragma unroll
                for (int k = 1; k < WIN; ++k) S += w[k];
                #pragma unroll
                for (int j = 0; j < 16; ++j) {
                    float den1 = denF[j];
                    float den2 = fmaf(KK, S, C12 - den1);
                    denF[j] = den1 * den2;
                    if (j < 15) S += w[j + WIN] - w[j];
                }
            }
            // Pass C: S = box sum of pt; num2 = 2k*S - num1 + (C1+C2); acc += num/den
            {
                const float4* b4 =
                    reinterpret_cast<const float4*>(&smem[A4_OFF + hrow * VS1 + xs]);
                float w[28];
                #pragma unroll
                for (int k = 0; k < 7; ++k) {
                    float4 u = b4[k];
                    w[4*k] = u.x; w[4*k+1] = u.y; w[4*k+2] = u.z; w[4*k+3] = u.w;
                }
                float S = w[0];
                #pragma unroll
                for (int k = 1; k < WIN; ++k) S += w[k];
                #pragma unroll
                for (int j = 0; j < 16; ++j) {
                    float n1 = numA[j];
                    float n2 = fmaf(2.0f * KK, S, C12 - n1);
                    float r = __fdividef(n1 * n2, denF[j]);
                    if (j < nvalid) acc += r;
                    if (j < 15) S += w[j + WIN] - w[j];
                }
            }
        }
        __syncthreads();
    }

    // ---------- deterministic block reduction ----------
    smem[threadIdx.x] = acc;
    __syncthreads();
    #pragma unroll
    for (int off = NTHREADS / 2; off > 0; off >>= 1) {
        if (threadIdx.x < off) smem[threadIdx.x] += smem[threadIdx.x + off];
        __syncthreads();
    }

    // ---------- fused finalize: last block reduces all partials ----------
    __shared__ bool s_last;
    if (threadIdx.x == 0) {
        g_partials[b] = smem[0];
        __threadfence();
        unsigned int n = atomicAdd(&g_count, 1u);
        s_last = (n == (unsigned int)(N_BLOCKS - 1));
    }
    __syncthreads();
    if (s_last) {
        double* sd = reinterpret_cast<double*>(smem);
        if (threadIdx.x < 64) {
            double s = 0.0;
            #pragma unroll
            for (int q = 0; q < 9; ++q)          // 64 * 9 = 576, fixed order
                s += (double)g_partials[threadIdx.x * 9 + q];
            sd[threadIdx.x] = s;
        }
        __syncthreads();
        #pragma unroll
        for (int off = 32; off > 0; off >>= 1) {
            if (threadIdx.x < off) sd[threadIdx.x] += sd[threadIdx.x + off];
            __syncthreads();
        }
        if (threadIdx.x == 0) {
            const double n = (double)N_PLANES * IMG_H * IMG_W;   // 23,592,960
            out[0] = (float)(1.0 - sd[0] / n);
            g_count = 0u;                         // reset for next graph replay
        }
    }
}

extern "C" void kernel_launch(void* const* d_in, const int* in_sizes, int n_in,
                              void* d_out, int out_size) {
    const float* pred = (const float*)d_in[0];
    const float* targ = (const float*)d_in[1];
    float* out = (float*)d_out;

    cudaFuncSetAttribute(ssim_main, cudaFuncAttributeMaxDynamicSharedMemorySize,
                         SMEM_BYTES);
    ssim_main<<<N_BLOCKS, NTHREADS, SMEM_BYTES>>>(pred, targ, out);
}